// round 2
// baseline (speedup 1.0000x reference)
#include <cuda_runtime.h>
#include <cuda_bf16.h>
#include <cstdint>

// Output = one_hot(arange(N), N) @ W = I @ W = W  (identity matmul).
// The whole problem is an 8 MiB device-to-device copy of W (16384 x 128 fp32).
//
// Round 1's hand-rolled grid-stride copy hit only 17% DRAM / 21% issue —
// request-generation-bound, not bandwidth-bound. Hand the copy to the
// driver's memcpy path (graph memcpy node / copy engine), which issues
// maximal-width bursts with deep MLP. cudaMemcpyAsync D2D is explicitly
// graph-capturable and allocation-free.

extern "C" void kernel_launch(void* const* d_in, const int* in_sizes, int n_in,
                              void* d_out, int out_size) {
    const void* W = d_in[0];
    size_t bytes = (size_t)out_size * sizeof(float);  // 16384*128*4 = 8 MiB
    cudaMemcpyAsync(d_out, W, bytes, cudaMemcpyDeviceToDevice, 0);
}

// round 3
// speedup vs baseline: 1.0437x; 1.0437x over previous
#include <cuda_runtime.h>
#include <cuda_bf16.h>
#include <cstdint>

// Output = one_hot(arange(N), N) @ W = I @ W = W: an 8 MiB D2D copy.
//
// R1 grid-stride copy: MLP~1/thread, issue=21%, DRAM=17.5% -> request-
// generation bound. R2 memcpy node: same ~6.8us (CE path no better).
// R3: explicit MLP. Each thread copies 4 independent float4s, loads
// front-batched (MLP_p1=4), no loop/branch. 524288 vec4 = 512 x 256 x 4
// exactly (N=16384, D=128 are static), so no bounds checks.

__global__ void __launch_bounds__(256) copy_w_mlp4(const float4* __restrict__ src,
                                                   float4* __restrict__ dst) {
    // Each CTA owns a contiguous 4*256-vec4 (16 KiB) tile; thread t handles
    // elements {base+t, base+t+256, base+t+512, base+t+768} -> fully coalesced.
    int base = blockIdx.x * (256 * 4) + threadIdx.x;

    // Front-batch 4 independent loads (MLP=4), then 4 stores.
    float4 a0 = src[base + 0 * 256];
    float4 a1 = src[base + 1 * 256];
    float4 a2 = src[base + 2 * 256];
    float4 a3 = src[base + 3 * 256];

    dst[base + 0 * 256] = a0;
    dst[base + 1 * 256] = a1;
    dst[base + 2 * 256] = a2;
    dst[base + 3 * 256] = a3;
}

extern "C" void kernel_launch(void* const* d_in, const int* in_sizes, int n_in,
                              void* d_out, int out_size) {
    const float4* W = (const float4*)d_in[0];
    float4* out = (float4*)d_out;
    // out_size = 16384*128 = 2097152 floats = 524288 vec4.
    // 524288 / (256 threads * 4 vec4) = 512 CTAs, exact.
    int blocks = out_size / (4 * 256 * 4);
    copy_w_mlp4<<<blocks, 256>>>(W, out);
}